// round 4
// baseline (speedup 1.0000x reference)
#include <cuda_runtime.h>
#include <cstdint>
#include <math.h>

#define BATCH 4
#define SEQ   4096
#define DIM   512
#define ROWS  (BATCH*SEQ)   // 16384
#define NCHUNK 32
#define CHUNK  128          // SEQ / NCHUNK
#define CLSZ   8            // cluster size for chain

// ---- scratch (no cudaMalloc allowed) ----
__device__ float g_R[ROWS*DIM];
__device__ float g_G[ROWS*DIM];
__device__ float g_C[ROWS*DIM];
__device__ float g_S[ROWS*DIM];
__device__ float g_cf[BATCH*NCHUNK*DIM];
__device__ float g_cp[BATCH*NCHUNK*DIM];

// ---------------- helpers ----------------
__device__ __forceinline__ uint32_t smem_u32(const void* p) {
    return (uint32_t)__cvta_generic_to_shared(p);
}
__device__ __forceinline__ void fma2(unsigned long long& d, unsigned long long a, unsigned long long b) {
    asm("fma.rn.f32x2 %0, %1, %2, %0;" : "+l"(d) : "l"(a), "l"(b));
}
__device__ __forceinline__ unsigned long long dupf(float a) {
    unsigned long long r;
    asm("mov.b64 %0, {%1, %1};" : "=l"(r) : "f"(a));
    return r;
}
__device__ __forceinline__ void unpack2(unsigned long long v, float& lo, float& hi) {
    asm("mov.b64 {%0, %1}, %2;" : "=f"(lo), "=f"(hi) : "l"(v));
}
__device__ __forceinline__ void mbar_init(uint32_t addr, uint32_t cnt) {
    asm volatile("mbarrier.init.shared.b64 [%0], %1;" :: "r"(addr), "r"(cnt) : "memory");
}
__device__ __forceinline__ void mbar_expect_tx(uint32_t addr, uint32_t bytes) {
    asm volatile("mbarrier.arrive.expect_tx.shared.b64 _, [%0], %1;" :: "r"(addr), "r"(bytes) : "memory");
}
__device__ __forceinline__ void st_async_u32(uint32_t raddr, uint32_t val, uint32_t rmbar) {
    asm volatile("st.async.weak.shared::cluster.mbarrier::complete_tx::bytes.b32 [%0], %1, [%2];"
                 :: "r"(raddr), "r"(val), "r"(rmbar) : "memory");
}
__device__ __forceinline__ void mbar_wait_cluster(uint32_t addr, uint32_t parity) {
    uint32_t done;
    asm volatile("{\n\t.reg .pred P;\n\t"
        "mbarrier.try_wait.parity.acquire.cluster.shared::cta.b64 P, [%1], %2, 0x989680;\n\t"
        "selp.b32 %0, 1, 0, P;\n\t}"
        : "=r"(done) : "r"(addr), "r"(parity) : "memory");
    while (!done) {
        asm volatile("{\n\t.reg .pred P;\n\t"
            "mbarrier.try_wait.parity.acquire.cluster.shared::cta.b64 P, [%1], %2, 0x989680;\n\t"
            "selp.b32 %0, 1, 0, P;\n\t}"
            : "=r"(done) : "r"(addr), "r"(parity) : "memory");
    }
}
#define CLUSTER_SYNC() do { \
    asm volatile("barrier.cluster.arrive.aligned;" ::: "memory"); \
    asm volatile("barrier.cluster.wait.aligned;"   ::: "memory"); } while (0)

// ============================================================
// Chunked linear scan for r
// ============================================================
__global__ void scan_local(const float* __restrict__ k, const float* __restrict__ v,
                           const float* __restrict__ decay, int store)
{
    int g = blockIdx.x*blockDim.x + threadIdx.x;
    int d = g % DIM;
    int c = (g / DIM) % NCHUNK;
    int b = g / (DIM*NCHUNK);
    float dec = decay[d >> 6];
    float r = store ? g_cp[g] : 0.0f;
    size_t base = ((size_t)b*SEQ + (size_t)c*CHUNK)*DIM + d;
    #pragma unroll 4
    for (int u = 0; u < CHUNK; u++) {
        size_t off = base + (size_t)u*DIM;
        r = fmaf(dec, r, k[off]*v[off]);
        if (store) g_R[off] = r;
    }
    if (!store) g_cf[g] = r;
}

__global__ void scan_prefix(const float* __restrict__ decay)
{
    int g = blockIdx.x*blockDim.x + threadIdx.x;
    int d = g % DIM;
    int b = g / DIM;
    float dec = decay[d >> 6];
    float dp = powf(dec, (float)CHUNK);
    float p = 0.0f;
    for (int c = 0; c < NCHUNK; c++) {
        int idx = (b*NCHUNK + c)*DIM + d;
        g_cp[idx] = p;
        p = g_cf[idx] + dp*p;
    }
}

// ============================================================
// GEMM: Y[M,512] = act(X[M,512] @ W[512,512]^T + bias), f32x2 inner
// ============================================================
__global__ __launch_bounds__(256)
void gemm_kernel(const float* __restrict__ X, const float* __restrict__ W,
                 const float* __restrict__ bias, float* __restrict__ Y, int act)
{
    __shared__ __align__(16) float Xs[16][132];
    __shared__ __align__(16) float Ws[16][132];
    const int K = DIM;
    int tid  = threadIdx.x;
    int m0   = blockIdx.y * 128;
    int n0   = blockIdx.x * 128;
    int rowc = (tid >> 4) << 3;
    int colc = (tid & 15) << 3;

    unsigned long long acc2[8][4];
    #pragma unroll
    for (int i = 0; i < 8; i++)
        #pragma unroll
        for (int j = 0; j < 4; j++) acc2[i][j] = 0ull;

    for (int kt = 0; kt < K; kt += 16) {
        #pragma unroll
        for (int l = 0; l < 2; l++) {
            int idx = tid + l*256;
            int row = idx >> 2;
            int fc  = (idx & 3) << 2;
            float4 xv = *(const float4*)(X + (size_t)(m0+row)*K + kt + fc);
            Xs[fc+0][row]=xv.x; Xs[fc+1][row]=xv.y; Xs[fc+2][row]=xv.z; Xs[fc+3][row]=xv.w;
            float4 wv = *(const float4*)(W + (size_t)(n0+row)*K + kt + fc);
            Ws[fc+0][row]=wv.x; Ws[fc+1][row]=wv.y; Ws[fc+2][row]=wv.z; Ws[fc+3][row]=wv.w;
        }
        __syncthreads();
        #pragma unroll
        for (int kk = 0; kk < 16; kk++) {
            float ar[8];
            *(float4*)(ar  ) = *(const float4*)&Xs[kk][rowc];
            *(float4*)(ar+4) = *(const float4*)&Xs[kk][rowc+4];
            ulonglong2 blo = *(const ulonglong2*)&Ws[kk][colc];
            ulonglong2 bhi = *(const ulonglong2*)&Ws[kk][colc+4];
            #pragma unroll
            for (int i = 0; i < 8; i++) {
                unsigned long long ad = dupf(ar[i]);
                fma2(acc2[i][0], ad, blo.x);
                fma2(acc2[i][1], ad, blo.y);
                fma2(acc2[i][2], ad, bhi.x);
                fma2(acc2[i][3], ad, bhi.y);
            }
        }
        __syncthreads();
    }

    #pragma unroll
    for (int i = 0; i < 8; i++) {
        float out[8];
        #pragma unroll
        for (int jp = 0; jp < 4; jp++) unpack2(acc2[i][jp], out[2*jp], out[2*jp+1]);
        #pragma unroll
        for (int j = 0; j < 8; j++) {
            float val = out[j] + (bias ? bias[n0+colc+j] : 0.0f);
            if (act == 1) val = 1.0f/(1.0f + expf(-val));
            Y[(size_t)(m0+rowc+i)*DIM + n0+colc+j] = val;
        }
    }
}

// ============================================================
// Sequential chain: 4 batches x 8-CTA clusters, 256 threads/CTA.
// Each thread: 1 output row slice-row (jl), k-part of 128 values
// held as 64 f32x2 A pairs in registers. 2-round shfl reduce.
// Direct st.async all-gather after a single __syncthreads.
// ============================================================
__global__ void __launch_bounds__(256, 1) __cluster_dims__(CLSZ, 1, 1)
chain_kernel(const float* __restrict__ q, const float* __restrict__ A,
             const float* __restrict__ G, const float* __restrict__ C,
             float* __restrict__ Sout)
{
    __shared__ __align__(16) float bl[2][DIM];            // double-buffered blended
    __shared__ __align__(8)  unsigned long long mbar[2];  // full-barrier per buffer

    int rank = blockIdx.x & (CLSZ-1);
    int b    = blockIdx.x / CLSZ;
    int tid  = threadIdx.x;
    int jl   = tid >> 2;       // 0..63 output row within slice
    int part = tid & 3;        // 0..3  k-partition (128 k each)
    int jg   = rank*64 + jl;   // global output row
    bool wr  = (part == 0);    // epilogue/writer lane

    uint32_t bl_a = smem_u32(&bl[0][0]);
    uint32_t mb_a = smem_u32(&mbar[0]);
    uint32_t dmb  = mb_a - bl_a;

    if (tid == 0) { mbar_init(mb_a, 1); mbar_init(mb_a + 8, 1); }

    // remote bl base of every cluster CTA
    uint32_t rb[CLSZ];
    #pragma unroll
    for (int r = 0; r < CLSZ; r++)
        asm("mapa.shared::cluster.u32 %0, %1, %2;" : "=r"(rb[r]) : "r"(bl_a), "r"(r));

    // A pairs: thread covers k = 4*(part + 4u)+{0..3}, u = 0..31  (128 floats)
    unsigned long long a2[64];
    #pragma unroll
    for (int u = 0; u < 32; u++) {
        ulonglong2 av = *(const ulonglong2*)(A + (size_t)jg*DIM + 4*(part + 4*u));
        a2[2*u] = av.x; a2[2*u+1] = av.y;
    }

    const float* qb = q    + (size_t)b*SEQ*DIM;
    const float* Gb = G    + (size_t)b*SEQ*DIM;
    const float* Cb = C    + (size_t)b*SEQ*DIM;
    float*       Sb = Sout + (size_t)b*SEQ*DIM;

    CLUSTER_SYNC();   // barriers initialized cluster-wide before any st.async

    float cc = 0.f, cg = 0.f, cq = 0.f;
    if (tid == 0) mbar_expect_tx(mb_a, 2048);
    if (wr) {
        float g0 = Gb[jg], q0 = qb[jg];
        uint32_t bits = __float_as_uint((1.0f - g0) * q0);   // state_0 = 0
        #pragma unroll
        for (int r = 0; r < CLSZ; r++)
            st_async_u32(rb[r] + (uint32_t)jg*4u, bits, rb[r] + dmb);
        cc = Cb[jg]; cg = Gb[DIM + jg]; cq = qb[DIM + jg];
    }

    for (int t = 0; t < SEQ; t++) {
        int p = t & 1;
        uint32_t ph = (t >> 1) & 1;

        // prefetch next operands + arm next buffer's barrier BEFORE waiting
        float nc = 0.f, ng = 0.f, nq = 0.f;
        if (wr) {
            if (t+1 < SEQ) nc = Cb[(size_t)(t+1)*DIM + jg];
            if (t+2 < SEQ) { ng = Gb[(size_t)(t+2)*DIM + jg]; nq = qb[(size_t)(t+2)*DIM + jg]; }
        }
        if (tid == 0 && t+1 < SEQ) mbar_expect_tx(mb_a + (uint32_t)(1-p)*8u, 2048);

        mbar_wait_cluster(mb_a + (uint32_t)p*8u, ph);

        // partial dot: 128 MACs/thread as 64 f32x2 FMAs
        unsigned long long acc0 = 0ull, acc1 = 0ull;
        const float* blp = bl[p];
        #pragma unroll
        for (int u = 0; u < 32; u++) {
            ulonglong2 bv = *(const ulonglong2*)(blp + 4*(part + 4*u));
            fma2(acc0, a2[2*u],   bv.x);
            fma2(acc1, a2[2*u+1], bv.y);
        }
        float x0, x1, y0, y1;
        unpack2(acc0, x0, x1);
        unpack2(acc1, y0, y1);
        float acc = (x0 + x1) + (y0 + y1);
        // reduce over 4 k-partitions (contiguous lanes)
        acc += __shfl_xor_sync(0xffffffffu, acc, 1);
        acc += __shfl_xor_sync(0xffffffffu, acc, 2);

        // epilogue compute BEFORE barrier (overlaps other warps arriving)
        uint32_t bits = 0u;
        if (wr) {
            float s = tanhf(acc + cc);
            Sb[(size_t)t*DIM + jg] = s;
            bits = __float_as_uint(fmaf(cg, s - cq, cq));   // g*s + (1-g)*q
            cc = nc; cg = ng; cq = nq;
        }

        // all warps done reading bl[p]; safe for peers' next stores
        __syncthreads();

        if (wr && t+1 < SEQ) {
            uint32_t boff = (uint32_t)(1-p)*2048u + (uint32_t)jg*4u;
            uint32_t moff = dmb + (uint32_t)(1-p)*8u;
            #pragma unroll
            for (int r = 0; r < CLSZ; r++)
                st_async_u32(rb[r] + boff, bits, rb[r] + moff);
        }
    }
}

// ============================================================
// launch
// ============================================================
extern "C" void kernel_launch(void* const* d_in, const int* in_sizes, int n_in,
                              void* d_out, int out_size)
{
    const float* q     = (const float*)d_in[0];
    const float* k     = (const float*)d_in[1];
    const float* v     = (const float*)d_in[2];
    const float* A     = (const float*)d_in[3];
    const float* Bm    = (const float*)d_in[4];
    const float* gw    = (const float*)d_in[5];
    const float* gb    = (const float*)d_in[6];
    const float* ow    = (const float*)d_in[7];
    const float* ob    = (const float*)d_in[8];
    const float* decay = (const float*)d_in[9];
    float* out = (float*)d_out;

    float *R, *G, *C, *S;
    cudaGetSymbolAddress((void**)&R, g_R);
    cudaGetSymbolAddress((void**)&G, g_G);
    cudaGetSymbolAddress((void**)&C, g_C);
    cudaGetSymbolAddress((void**)&S, g_S);

    // 1) chunked linear scan for r
    scan_local <<<BATCH*NCHUNK*DIM/256, 256>>>(k, v, decay, 0);
    scan_prefix<<<BATCH*DIM/256,        256>>>(decay);
    scan_local <<<BATCH*NCHUNK*DIM/256, 256>>>(k, v, decay, 1);

    dim3 ggrid(DIM/128, ROWS/128);
    // 2) gates (sigmoid epilogue)
    gemm_kernel<<<ggrid, 256>>>(q, gw, gb, G, 1);
    // 3) C = R @ Bm^T
    gemm_kernel<<<ggrid, 256>>>(R, Bm, nullptr, C, 0);
    // 4) sequential recurrent chain (4 clusters of 8 CTAs)
    chain_kernel<<<BATCH*CLSZ, 256>>>(q, A, G, C, S);
    // 5) out projection
    gemm_kernel<<<ggrid, 256>>>(S, ow, ob, out, 0);
}

// round 5
// speedup vs baseline: 1.3207x; 1.3207x over previous
#include <cuda_runtime.h>
#include <cstdint>
#include <math.h>

#define BATCH 4
#define SEQ   4096
#define DIM   512
#define ROWS  (BATCH*SEQ)   // 16384
#define NCHUNK 32
#define CHUNK  128          // SEQ / NCHUNK
#define CLSZ   8            // cluster size for chain

// ---- scratch (no cudaMalloc allowed) ----
__device__ float g_R[ROWS*DIM];
__device__ float g_G[ROWS*DIM];
__device__ float g_C[ROWS*DIM];
__device__ float g_S[ROWS*DIM];
__device__ float g_cf[BATCH*NCHUNK*DIM];
__device__ float g_cp[BATCH*NCHUNK*DIM];

// ---------------- helpers ----------------
__device__ __forceinline__ uint32_t smem_u32(const void* p) {
    return (uint32_t)__cvta_generic_to_shared(p);
}
__device__ __forceinline__ void fma2(unsigned long long& d, unsigned long long a, unsigned long long b) {
    asm("fma.rn.f32x2 %0, %1, %2, %0;" : "+l"(d) : "l"(a), "l"(b));
}
__device__ __forceinline__ unsigned long long dupf(float a) {
    unsigned long long r;
    asm("mov.b64 %0, {%1, %1};" : "=l"(r) : "f"(a));
    return r;
}
__device__ __forceinline__ void unpack2(unsigned long long v, float& lo, float& hi) {
    asm("mov.b64 {%0, %1}, %2;" : "=f"(lo), "=f"(hi) : "l"(v));
}
__device__ __forceinline__ void mbar_init(uint32_t addr, uint32_t cnt) {
    asm volatile("mbarrier.init.shared.b64 [%0], %1;" :: "r"(addr), "r"(cnt) : "memory");
}
__device__ __forceinline__ void mbar_expect_tx(uint32_t addr, uint32_t bytes) {
    asm volatile("mbarrier.arrive.expect_tx.shared.b64 _, [%0], %1;" :: "r"(addr), "r"(bytes) : "memory");
}
__device__ __forceinline__ void st_async_u32(uint32_t raddr, uint32_t val, uint32_t rmbar) {
    asm volatile("st.async.weak.shared::cluster.mbarrier::complete_tx::bytes.b32 [%0], %1, [%2];"
                 :: "r"(raddr), "r"(val), "r"(rmbar) : "memory");
}
__device__ __forceinline__ void mbar_wait_cluster(uint32_t addr, uint32_t parity) {
    uint32_t done;
    asm volatile("{\n\t.reg .pred P;\n\t"
        "mbarrier.try_wait.parity.acquire.cluster.shared::cta.b64 P, [%1], %2, 0x989680;\n\t"
        "selp.b32 %0, 1, 0, P;\n\t}"
        : "=r"(done) : "r"(addr), "r"(parity) : "memory");
    while (!done) {
        asm volatile("{\n\t.reg .pred P;\n\t"
            "mbarrier.try_wait.parity.acquire.cluster.shared::cta.b64 P, [%1], %2, 0x989680;\n\t"
            "selp.b32 %0, 1, 0, P;\n\t}"
            : "=r"(done) : "r"(addr), "r"(parity) : "memory");
    }
}
#define CLUSTER_SYNC() do { \
    asm volatile("barrier.cluster.arrive.aligned;" ::: "memory"); \
    asm volatile("barrier.cluster.wait.aligned;"   ::: "memory"); } while (0)

// ============================================================
// Chunked linear scan for r
// ============================================================
__global__ void scan_local(const float* __restrict__ k, const float* __restrict__ v,
                           const float* __restrict__ decay, int store)
{
    int g = blockIdx.x*blockDim.x + threadIdx.x;
    int d = g % DIM;
    int c = (g / DIM) % NCHUNK;
    int b = g / (DIM*NCHUNK);
    float dec = decay[d >> 6];
    float r = store ? g_cp[g] : 0.0f;
    size_t base = ((size_t)b*SEQ + (size_t)c*CHUNK)*DIM + d;
    #pragma unroll 4
    for (int u = 0; u < CHUNK; u++) {
        size_t off = base + (size_t)u*DIM;
        r = fmaf(dec, r, k[off]*v[off]);
        if (store) g_R[off] = r;
    }
    if (!store) g_cf[g] = r;
}

__global__ void scan_prefix(const float* __restrict__ decay)
{
    int g = blockIdx.x*blockDim.x + threadIdx.x;
    int d = g % DIM;
    int b = g / DIM;
    float dec = decay[d >> 6];
    float dp = powf(dec, (float)CHUNK);
    float p = 0.0f;
    for (int c = 0; c < NCHUNK; c++) {
        int idx = (b*NCHUNK + c)*DIM + d;
        g_cp[idx] = p;
        p = g_cf[idx] + dp*p;
    }
}

// ============================================================
// GEMM: Y[M,512] = act(X[M,512] @ W[512,512]^T + bias), f32x2 inner
// ============================================================
__global__ __launch_bounds__(256)
void gemm_kernel(const float* __restrict__ X, const float* __restrict__ W,
                 const float* __restrict__ bias, float* __restrict__ Y, int act)
{
    __shared__ __align__(16) float Xs[16][132];
    __shared__ __align__(16) float Ws[16][132];
    const int K = DIM;
    int tid  = threadIdx.x;
    int m0   = blockIdx.y * 128;
    int n0   = blockIdx.x * 128;
    int rowc = (tid >> 4) << 3;
    int colc = (tid & 15) << 3;

    unsigned long long acc2[8][4];
    #pragma unroll
    for (int i = 0; i < 8; i++)
        #pragma unroll
        for (int j = 0; j < 4; j++) acc2[i][j] = 0ull;

    for (int kt = 0; kt < K; kt += 16) {
        #pragma unroll
        for (int l = 0; l < 2; l++) {
            int idx = tid + l*256;
            int row = idx >> 2;
            int fc  = (idx & 3) << 2;
            float4 xv = *(const float4*)(X + (size_t)(m0+row)*K + kt + fc);
            Xs[fc+0][row]=xv.x; Xs[fc+1][row]=xv.y; Xs[fc+2][row]=xv.z; Xs[fc+3][row]=xv.w;
            float4 wv = *(const float4*)(W + (size_t)(n0+row)*K + kt + fc);
            Ws[fc+0][row]=wv.x; Ws[fc+1][row]=wv.y; Ws[fc+2][row]=wv.z; Ws[fc+3][row]=wv.w;
        }
        __syncthreads();
        #pragma unroll
        for (int kk = 0; kk < 16; kk++) {
            float ar[8];
            *(float4*)(ar  ) = *(const float4*)&Xs[kk][rowc];
            *(float4*)(ar+4) = *(const float4*)&Xs[kk][rowc+4];
            ulonglong2 blo = *(const ulonglong2*)&Ws[kk][colc];
            ulonglong2 bhi = *(const ulonglong2*)&Ws[kk][colc+4];
            #pragma unroll
            for (int i = 0; i < 8; i++) {
                unsigned long long ad = dupf(ar[i]);
                fma2(acc2[i][0], ad, blo.x);
                fma2(acc2[i][1], ad, blo.y);
                fma2(acc2[i][2], ad, bhi.x);
                fma2(acc2[i][3], ad, bhi.y);
            }
        }
        __syncthreads();
    }

    #pragma unroll
    for (int i = 0; i < 8; i++) {
        float out[8];
        #pragma unroll
        for (int jp = 0; jp < 4; jp++) unpack2(acc2[i][jp], out[2*jp], out[2*jp+1]);
        #pragma unroll
        for (int j = 0; j < 8; j++) {
            float val = out[j] + (bias ? bias[n0+colc+j] : 0.0f);
            if (act == 1) val = 1.0f/(1.0f + expf(-val));
            Y[(size_t)(m0+rowc+i)*DIM + n0+colc+j] = val;
        }
    }
}

// ============================================================
// Sequential chain: 4 batches x 8-CTA clusters, 256 threads/CTA.
// BROADCAST layout: lane = output row, warp owns a k-quarter.
// All lanes of a warp read the SAME bl address (LDS broadcast, N=1)
// -> SMEM traffic/step drops 131KB -> 8KB (crossbar was the bound).
// Partials reduced via smem part[4][64]; 64 epilogue threads finish.
// ============================================================
__global__ void __launch_bounds__(256, 1) __cluster_dims__(CLSZ, 1, 1)
chain_kernel(const float* __restrict__ q, const float* __restrict__ A,
             const float* __restrict__ G, const float* __restrict__ C,
             float* __restrict__ Sout)
{
    __shared__ __align__(16) float bl[2][DIM];            // double-buffered blended
    __shared__ __align__(16) float part[4][64];           // per-quarter partials
    __shared__ __align__(8)  unsigned long long mbar[2];  // full-barrier per buffer

    int rank = blockIdx.x & (CLSZ-1);
    int b    = blockIdx.x / CLSZ;
    int tid  = threadIdx.x;
    int w    = tid >> 5;
    int lane = tid & 31;
    int qw   = w >> 1;            // k-quarter (0..3), 128 k each
    int rh   = w & 1;             // row-half (0..1)
    int jl   = rh*32 + lane;      // output row within slice (0..63)
    int jg   = rank*64 + jl;      // global output row
    int kbase= qw*128;

    uint32_t bl_a = smem_u32(&bl[0][0]);
    uint32_t mb_a = smem_u32(&mbar[0]);
    uint32_t dmb  = mb_a - bl_a;

    if (tid == 0) { mbar_init(mb_a, 1); mbar_init(mb_a + 8, 1); }

    // remote bl base of every cluster CTA
    uint32_t rb[CLSZ];
    #pragma unroll
    for (int r = 0; r < CLSZ; r++)
        asm("mapa.shared::cluster.u32 %0, %1, %2;" : "=r"(rb[r]) : "r"(bl_a), "r"(r));

    // A slice in registers: row jg, k in [kbase, kbase+128)
    unsigned long long a2[64];
    #pragma unroll
    for (int u = 0; u < 32; u++) {
        ulonglong2 av = *(const ulonglong2*)(A + (size_t)jg*DIM + kbase + 4*u);
        a2[2*u] = av.x; a2[2*u+1] = av.y;
    }

    const float* qb = q    + (size_t)b*SEQ*DIM;
    const float* Gb = G    + (size_t)b*SEQ*DIM;
    const float* Cb = C    + (size_t)b*SEQ*DIM;
    float*       Sb = Sout + (size_t)b*SEQ*DIM;

    CLUSTER_SYNC();   // barriers initialized cluster-wide before any st.async

    // epilogue lanes: tid < 64, output row = tid
    int je = rank*64 + tid;           // valid when tid < 64
    float cc = 0.f, cg = 0.f, cq = 0.f;
    if (tid == 0) mbar_expect_tx(mb_a, 2048);
    if (tid < 64) {
        float g0 = Gb[je], q0 = qb[je];
        uint32_t bits = __float_as_uint((1.0f - g0) * q0);   // state_0 = 0
        #pragma unroll
        for (int r = 0; r < CLSZ; r++)
            st_async_u32(rb[r] + (uint32_t)je*4u, bits, rb[r] + dmb);
        cc = Cb[je]; cg = Gb[DIM + je]; cq = qb[DIM + je];
    }

    for (int t = 0; t < SEQ; t++) {
        int p = t & 1;
        uint32_t ph = (t >> 1) & 1;

        // prefetch next operands + arm next buffer's barrier BEFORE waiting
        float nc = 0.f, ng = 0.f, nq = 0.f;
        if (tid < 64) {
            if (t+1 < SEQ) nc = Cb[(size_t)(t+1)*DIM + je];
            if (t+2 < SEQ) { ng = Gb[(size_t)(t+2)*DIM + je]; nq = qb[(size_t)(t+2)*DIM + je]; }
        }
        if (tid == 0 && t+1 < SEQ) mbar_expect_tx(mb_a + (uint32_t)(1-p)*8u, 2048);

        mbar_wait_cluster(mb_a + (uint32_t)p*8u, ph);

        // 128 MACs/thread; bl reads are warp-uniform -> broadcast LDS
        unsigned long long acc0 = 0ull, acc1 = 0ull;
        const float* blp = bl[p] + kbase;
        #pragma unroll
        for (int u = 0; u < 32; u++) {
            ulonglong2 bv = *(const ulonglong2*)(blp + 4*u);
            fma2(acc0, a2[2*u],   bv.x);
            fma2(acc1, a2[2*u+1], bv.y);
        }
        float x0, x1, y0, y1;
        unpack2(acc0, x0, x1);
        unpack2(acc1, y0, y1);
        part[qw][jl] = (x0 + x1) + (y0 + y1);

        // all warps done reading bl[p] + partials published
        __syncthreads();

        if (tid < 64) {
            float acc = (part[0][tid] + part[1][tid]) + (part[2][tid] + part[3][tid]);
            float s = tanhf(acc + cc);
            Sb[(size_t)t*DIM + je] = s;
            if (t+1 < SEQ) {
                uint32_t bits = __float_as_uint(fmaf(cg, s - cq, cq)); // g*s+(1-g)*q
                uint32_t boff = (uint32_t)(1-p)*2048u + (uint32_t)je*4u;
                uint32_t moff = dmb + (uint32_t)(1-p)*8u;
                #pragma unroll
                for (int r = 0; r < CLSZ; r++)
                    st_async_u32(rb[r] + boff, bits, rb[r] + moff);
            }
            cc = nc; cg = ng; cq = nq;
        }
    }
}

// ============================================================
// launch
// ============================================================
extern "C" void kernel_launch(void* const* d_in, const int* in_sizes, int n_in,
                              void* d_out, int out_size)
{
    const float* q     = (const float*)d_in[0];
    const float* k     = (const float*)d_in[1];
    const float* v     = (const float*)d_in[2];
    const float* A     = (const float*)d_in[3];
    const float* Bm    = (const float*)d_in[4];
    const float* gw    = (const float*)d_in[5];
    const float* gb    = (const float*)d_in[6];
    const float* ow    = (const float*)d_in[7];
    const float* ob    = (const float*)d_in[8];
    const float* decay = (const float*)d_in[9];
    float* out = (float*)d_out;

    float *R, *G, *C, *S;
    cudaGetSymbolAddress((void**)&R, g_R);
    cudaGetSymbolAddress((void**)&G, g_G);
    cudaGetSymbolAddress((void**)&C, g_C);
    cudaGetSymbolAddress((void**)&S, g_S);

    // 1) chunked linear scan for r
    scan_local <<<BATCH*NCHUNK*DIM/256, 256>>>(k, v, decay, 0);
    scan_prefix<<<BATCH*DIM/256,        256>>>(decay);
    scan_local <<<BATCH*NCHUNK*DIM/256, 256>>>(k, v, decay, 1);

    dim3 ggrid(DIM/128, ROWS/128);
    // 2) gates (sigmoid epilogue)
    gemm_kernel<<<ggrid, 256>>>(q, gw, gb, G, 1);
    // 3) C = R @ Bm^T
    gemm_kernel<<<ggrid, 256>>>(R, Bm, nullptr, C, 0);
    // 4) sequential recurrent chain (4 clusters of 8 CTAs)
    chain_kernel<<<BATCH*CLSZ, 256>>>(q, A, G, C, S);
    // 5) out projection
    gemm_kernel<<<ggrid, 256>>>(S, ow, ob, out, 0);
}

// round 6
// speedup vs baseline: 1.3241x; 1.0026x over previous
#include <cuda_runtime.h>
#include <cstdint>
#include <math.h>

#define BATCH 4
#define SEQ   4096
#define DIM   512
#define ROWS  (BATCH*SEQ)   // 16384
#define NCHUNK 32
#define CHUNK  128          // SEQ / NCHUNK
#define CLSZ   8            // cluster size for chain

// ---- scratch (no cudaMalloc allowed) ----
__device__ float g_R[ROWS*DIM];
__device__ float g_G[ROWS*DIM];
__device__ float g_C[ROWS*DIM];
__device__ float g_S[ROWS*DIM];
__device__ float g_cf[BATCH*NCHUNK*DIM];
__device__ float g_cp[BATCH*NCHUNK*DIM];

// ---------------- helpers ----------------
__device__ __forceinline__ uint32_t smem_u32(const void* p) {
    return (uint32_t)__cvta_generic_to_shared(p);
}
__device__ __forceinline__ void fma2(unsigned long long& d, unsigned long long a, unsigned long long b) {
    asm("fma.rn.f32x2 %0, %1, %2, %0;" : "+l"(d) : "l"(a), "l"(b));
}
__device__ __forceinline__ unsigned long long dupf(float a) {
    unsigned long long r;
    asm("mov.b64 %0, {%1, %1};" : "=l"(r) : "f"(a));
    return r;
}
__device__ __forceinline__ void unpack2(unsigned long long v, float& lo, float& hi) {
    asm("mov.b64 {%0, %1}, %2;" : "=f"(lo), "=f"(hi) : "l"(v));
}
__device__ __forceinline__ void mbar_init(uint32_t addr, uint32_t cnt) {
    asm volatile("mbarrier.init.shared.b64 [%0], %1;" :: "r"(addr), "r"(cnt) : "memory");
}
__device__ __forceinline__ void mbar_expect_tx(uint32_t addr, uint32_t bytes) {
    asm volatile("mbarrier.arrive.expect_tx.shared.b64 _, [%0], %1;" :: "r"(addr), "r"(bytes) : "memory");
}
__device__ __forceinline__ void st_async_u32(uint32_t raddr, uint32_t val, uint32_t rmbar) {
    asm volatile("st.async.weak.shared::cluster.mbarrier::complete_tx::bytes.b32 [%0], %1, [%2];"
                 :: "r"(raddr), "r"(val), "r"(rmbar) : "memory");
}
__device__ __forceinline__ void mbar_wait_cluster(uint32_t addr, uint32_t parity) {
    uint32_t done;
    asm volatile("{\n\t.reg .pred P;\n\t"
        "mbarrier.try_wait.parity.acquire.cluster.shared::cta.b64 P, [%1], %2, 0x989680;\n\t"
        "selp.b32 %0, 1, 0, P;\n\t}"
        : "=r"(done) : "r"(addr), "r"(parity) : "memory");
    while (!done) {
        asm volatile("{\n\t.reg .pred P;\n\t"
            "mbarrier.try_wait.parity.acquire.cluster.shared::cta.b64 P, [%1], %2, 0x989680;\n\t"
            "selp.b32 %0, 1, 0, P;\n\t}"
            : "=r"(done) : "r"(addr), "r"(parity) : "memory");
    }
}
#define CLUSTER_SYNC() do { \
    asm volatile("barrier.cluster.arrive.aligned;" ::: "memory"); \
    asm volatile("barrier.cluster.wait.aligned;"   ::: "memory"); } while (0)

// ============================================================
// Chunked linear scan for r
// ============================================================
__global__ void scan_local(const float* __restrict__ k, const float* __restrict__ v,
                           const float* __restrict__ decay, int store)
{
    int g = blockIdx.x*blockDim.x + threadIdx.x;
    int d = g % DIM;
    int c = (g / DIM) % NCHUNK;
    int b = g / (DIM*NCHUNK);
    float dec = decay[d >> 6];
    float r = store ? g_cp[g] : 0.0f;
    size_t base = ((size_t)b*SEQ + (size_t)c*CHUNK)*DIM + d;
    #pragma unroll 4
    for (int u = 0; u < CHUNK; u++) {
        size_t off = base + (size_t)u*DIM;
        r = fmaf(dec, r, k[off]*v[off]);
        if (store) g_R[off] = r;
    }
    if (!store) g_cf[g] = r;
}

__global__ void scan_prefix(const float* __restrict__ decay)
{
    int g = blockIdx.x*blockDim.x + threadIdx.x;
    int d = g % DIM;
    int b = g / DIM;
    float dec = decay[d >> 6];
    float dp = powf(dec, (float)CHUNK);
    float p = 0.0f;
    for (int c = 0; c < NCHUNK; c++) {
        int idx = (b*NCHUNK + c)*DIM + d;
        g_cp[idx] = p;
        p = g_cf[idx] + dp*p;
    }
}

// ============================================================
// GEMM: Y[M,512] = act(X[M,512] @ W[512,512]^T + bias), f32x2 inner
// ============================================================
__global__ __launch_bounds__(256)
void gemm_kernel(const float* __restrict__ X, const float* __restrict__ W,
                 const float* __restrict__ bias, float* __restrict__ Y, int act)
{
    __shared__ __align__(16) float Xs[16][132];
    __shared__ __align__(16) float Ws[16][132];
    const int K = DIM;
    int tid  = threadIdx.x;
    int m0   = blockIdx.y * 128;
    int n0   = blockIdx.x * 128;
    int rowc = (tid >> 4) << 3;
    int colc = (tid & 15) << 3;

    unsigned long long acc2[8][4];
    #pragma unroll
    for (int i = 0; i < 8; i++)
        #pragma unroll
        for (int j = 0; j < 4; j++) acc2[i][j] = 0ull;

    for (int kt = 0; kt < K; kt += 16) {
        #pragma unroll
        for (int l = 0; l < 2; l++) {
            int idx = tid + l*256;
            int row = idx >> 2;
            int fc  = (idx & 3) << 2;
            float4 xv = *(const float4*)(X + (size_t)(m0+row)*K + kt + fc);
            Xs[fc+0][row]=xv.x; Xs[fc+1][row]=xv.y; Xs[fc+2][row]=xv.z; Xs[fc+3][row]=xv.w;
            float4 wv = *(const float4*)(W + (size_t)(n0+row)*K + kt + fc);
            Ws[fc+0][row]=wv.x; Ws[fc+1][row]=wv.y; Ws[fc+2][row]=wv.z; Ws[fc+3][row]=wv.w;
        }
        __syncthreads();
        #pragma unroll
        for (int kk = 0; kk < 16; kk++) {
            float ar[8];
            *(float4*)(ar  ) = *(const float4*)&Xs[kk][rowc];
            *(float4*)(ar+4) = *(const float4*)&Xs[kk][rowc+4];
            ulonglong2 blo = *(const ulonglong2*)&Ws[kk][colc];
            ulonglong2 bhi = *(const ulonglong2*)&Ws[kk][colc+4];
            #pragma unroll
            for (int i = 0; i < 8; i++) {
                unsigned long long ad = dupf(ar[i]);
                fma2(acc2[i][0], ad, blo.x);
                fma2(acc2[i][1], ad, blo.y);
                fma2(acc2[i][2], ad, bhi.x);
                fma2(acc2[i][3], ad, bhi.y);
            }
        }
        __syncthreads();
    }

    #pragma unroll
    for (int i = 0; i < 8; i++) {
        float out[8];
        #pragma unroll
        for (int jp = 0; jp < 4; jp++) unpack2(acc2[i][jp], out[2*jp], out[2*jp+1]);
        #pragma unroll
        for (int j = 0; j < 8; j++) {
            float val = out[j] + (bias ? bias[n0+colc+j] : 0.0f);
            if (act == 1) val = 1.0f/(1.0f + expf(-val));
            Y[(size_t)(m0+rowc+i)*DIM + n0+colc+j] = val;
        }
    }
}

// ============================================================
// Sequential chain: 4 batches x 8-CTA clusters, 256 threads/CTA.
// Broadcast MAC layout (R5) + HALF-SPLIT barriers (R6):
//   blended rows [0,256) come only from CTAs 0-3, [256,512) from 4-7.
//   Each warp consumes one k-quarter -> one half; it waits ONLY on
//   that half's barrier, so MAC on the first-arriving half overlaps
//   DSMEM transit of the second.
// ============================================================
__global__ void __launch_bounds__(256, 1) __cluster_dims__(CLSZ, 1, 1)
chain_kernel(const float* __restrict__ q, const float* __restrict__ A,
             const float* __restrict__ G, const float* __restrict__ C,
             float* __restrict__ Sout)
{
    __shared__ __align__(16) float bl[2][DIM];            // double-buffered blended
    __shared__ __align__(16) float part[4][64];           // per-quarter partials
    __shared__ __align__(8)  unsigned long long mbar[4];  // [buf][half]

    int rank = blockIdx.x & (CLSZ-1);
    int b    = blockIdx.x / CLSZ;
    int tid  = threadIdx.x;
    int w    = tid >> 5;
    int lane = tid & 31;
    int qw   = w >> 1;            // k-quarter (0..3), 128 k each
    int rh   = w & 1;             // row-half (0..1)
    int jl   = rh*32 + lane;      // output row within slice (0..63)
    int jg   = rank*64 + jl;      // global output row
    int kbase= qw*128;
    int hw   = qw >> 1;           // half this warp CONSUMES (0 or 1)
    int myh  = rank >> 2;         // half this CTA PRODUCES

    uint32_t bl_a = smem_u32(&bl[0][0]);
    uint32_t mb_a = smem_u32(&mbar[0]);
    uint32_t dmb  = mb_a - bl_a;

    if (tid == 0) {
        mbar_init(mb_a,      1);  // buf0 half0
        mbar_init(mb_a + 8,  1);  // buf0 half1
        mbar_init(mb_a + 16, 1);  // buf1 half0
        mbar_init(mb_a + 24, 1);  // buf1 half1
    }

    // remote bl base of every cluster CTA
    uint32_t rb[CLSZ];
    #pragma unroll
    for (int r = 0; r < CLSZ; r++)
        asm("mapa.shared::cluster.u32 %0, %1, %2;" : "=r"(rb[r]) : "r"(bl_a), "r"(r));

    // A slice in registers: row jg, k in [kbase, kbase+128)
    unsigned long long a2[64];
    #pragma unroll
    for (int u = 0; u < 32; u++) {
        ulonglong2 av = *(const ulonglong2*)(A + (size_t)jg*DIM + kbase + 4*u);
        a2[2*u] = av.x; a2[2*u+1] = av.y;
    }

    const float* qb = q    + (size_t)b*SEQ*DIM;
    const float* Gb = G    + (size_t)b*SEQ*DIM;
    const float* Cb = C    + (size_t)b*SEQ*DIM;
    float*       Sb = Sout + (size_t)b*SEQ*DIM;

    CLUSTER_SYNC();   // barriers initialized cluster-wide before any st.async

    // epilogue lanes: tid < 64, output row = tid
    int je = rank*64 + tid;           // valid when tid < 64
    float cc = 0.f, cg = 0.f, cq = 0.f;
    if (tid == 0) {                   // arm both halves of buffer 0
        mbar_expect_tx(mb_a,     1024);
        mbar_expect_tx(mb_a + 8, 1024);
    }
    if (tid < 64) {
        float g0 = Gb[je], q0 = qb[je];
        uint32_t bits = __float_as_uint((1.0f - g0) * q0);   // state_0 = 0
        uint32_t moff = dmb + (uint32_t)myh*8u;              // buf0, half myh
        #pragma unroll
        for (int r = 0; r < CLSZ; r++)
            st_async_u32(rb[r] + (uint32_t)je*4u, bits, rb[r] + moff);
        cc = Cb[je]; cg = Gb[DIM + je]; cq = qb[DIM + je];
    }

    for (int t = 0; t < SEQ; t++) {
        int p = t & 1;
        uint32_t ph = (t >> 1) & 1;

        // prefetch next operands + arm next buffer's barriers BEFORE waiting
        float nc = 0.f, ng = 0.f, nq = 0.f;
        if (tid < 64) {
            if (t+1 < SEQ) nc = Cb[(size_t)(t+1)*DIM + je];
            if (t+2 < SEQ) { ng = Gb[(size_t)(t+2)*DIM + je]; nq = qb[(size_t)(t+2)*DIM + je]; }
        }
        if (tid == 0 && t+1 < SEQ) {
            mbar_expect_tx(mb_a + (uint32_t)(1-p)*16u,      1024);
            mbar_expect_tx(mb_a + (uint32_t)(1-p)*16u + 8u, 1024);
        }

        // wait only for the half this warp consumes
        mbar_wait_cluster(mb_a + (uint32_t)p*16u + (uint32_t)hw*8u, ph);

        // 128 MACs/thread; bl reads are warp-uniform -> broadcast LDS
        unsigned long long acc0 = 0ull, acc1 = 0ull;
        const float* blp = bl[p] + kbase;
        #pragma unroll
        for (int u = 0; u < 32; u++) {
            ulonglong2 bv = *(const ulonglong2*)(blp + 4*u);
            fma2(acc0, a2[2*u],   bv.x);
            fma2(acc1, a2[2*u+1], bv.y);
        }
        float x0, x1, y0, y1;
        unpack2(acc0, x0, x1);
        unpack2(acc1, y0, y1);
        part[qw][jl] = (x0 + x1) + (y0 + y1);

        // all warps done reading bl[p] + partials published
        __syncthreads();

        if (tid < 64) {
            float acc = (part[0][tid] + part[1][tid]) + (part[2][tid] + part[3][tid]);
            float s = tanhf(acc + cc);
            Sb[(size_t)t*DIM + je] = s;
            if (t+1 < SEQ) {
                uint32_t bits = __float_as_uint(fmaf(cg, s - cq, cq)); // g*s+(1-g)*q
                uint32_t boff = (uint32_t)(1-p)*2048u + (uint32_t)je*4u;
                uint32_t moff = dmb + (uint32_t)(1-p)*16u + (uint32_t)myh*8u;
                #pragma unroll
                for (int r = 0; r < CLSZ; r++)
                    st_async_u32(rb[r] + boff, bits, rb[r] + moff);
            }
            cc = nc; cg = ng; cq = nq;
        }
    }
}

// ============================================================
// launch
// ============================================================
extern "C" void kernel_launch(void* const* d_in, const int* in_sizes, int n_in,
                              void* d_out, int out_size)
{
    const float* q     = (const float*)d_in[0];
    const float* k     = (const float*)d_in[1];
    const float* v     = (const float*)d_in[2];
    const float* A     = (const float*)d_in[3];
    const float* Bm    = (const float*)d_in[4];
    const float* gw    = (const float*)d_in[5];
    const float* gb    = (const float*)d_in[6];
    const float* ow    = (const float*)d_in[7];
    const float* ob    = (const float*)d_in[8];
    const float* decay = (const float*)d_in[9];
    float* out = (float*)d_out;

    float *R, *G, *C, *S;
    cudaGetSymbolAddress((void**)&R, g_R);
    cudaGetSymbolAddress((void**)&G, g_G);
    cudaGetSymbolAddress((void**)&C, g_C);
    cudaGetSymbolAddress((void**)&S, g_S);

    // 1) chunked linear scan for r
    scan_local <<<BATCH*NCHUNK*DIM/256, 256>>>(k, v, decay, 0);
    scan_prefix<<<BATCH*DIM/256,        256>>>(decay);
    scan_local <<<BATCH*NCHUNK*DIM/256, 256>>>(k, v, decay, 1);

    dim3 ggrid(DIM/128, ROWS/128);
    // 2) gates (sigmoid epilogue)
    gemm_kernel<<<ggrid, 256>>>(q, gw, gb, G, 1);
    // 3) C = R @ Bm^T
    gemm_kernel<<<ggrid, 256>>>(R, Bm, nullptr, C, 0);
    // 4) sequential recurrent chain (4 clusters of 8 CTAs)
    chain_kernel<<<BATCH*CLSZ, 256>>>(q, A, G, C, S);
    // 5) out projection
    gemm_kernel<<<ggrid, 256>>>(S, ow, ob, out, 0);
}